// round 4
// baseline (speedup 1.0000x reference)
#include <cuda_runtime.h>
#include <math.h>

#define N_NODES 200
#define NM1     199
#define E_TOT   39800

typedef unsigned long long u64;

__device__ __forceinline__ u64 pack2(float lo, float hi) {
    u64 r; asm("mov.b64 %0,{%1,%2};" : "=l"(r) : "f"(lo), "f"(hi)); return r;
}
__device__ __forceinline__ void unpack2(u64 v, float& lo, float& hi) {
    asm("mov.b64 {%0,%1},%2;" : "=f"(lo), "=f"(hi) : "l"(v));
}
__device__ __forceinline__ void ffma2(u64& d, u64 a, u64 b) {
    asm("fma.rn.f32x2 %0,%1,%2,%0;" : "+l"(d) : "l"(a), "l"(b));
}

// ---------------- scratch (device globals; no allocation) ----------------
__device__ __align__(16) float g_part[16 * 200 * 512];
__device__ __align__(16) float g_h1[200 * 512];
__device__ __align__(16) float g_h2[200 * 256];
__device__ __align__(16) float g_G [200 * 512];      // [n][h*4+o]
__device__ __align__(16) float g_c [200 * 4];
__device__ __align__(16) float g_P [200 * 4];        // root-head part
__device__ __align__(16) float g_msg[E_TOT * 4];
__device__ __align__(16) float g_W3G [257 * 512];    // row256 = bias row
__device__ __align__(16) float g_W3CH[257 * 12];     // row256 = bias row
__device__ __align__(16) float g_A [200 * 256];      // attr@we1[0:8]+be1
__device__ __align__(16) float g_B [200 * 256];      // attr@we1[8:16]

#define BM 16
#define BN 64
#define BK 16

// ---------------- generic split-K GEMM (partials) ----------------
__global__ void __launch_bounds__(128)
gemm_kernel(const float* __restrict__ A, const float* __restrict__ B,
            float* __restrict__ out, int M, int N, int K, int nsplit) {
    __shared__ __align__(16) float As[BK * BM];
    __shared__ __align__(16) float Bs[BK * BN];
    int t = threadIdx.x;
    int tx = t & 15, ty = t >> 4;
    int col0 = blockIdx.x * BN, row0 = blockIdx.y * BM;
    int kc = K / nsplit;
    int k0 = blockIdx.z * kc, k1 = k0 + kc;

    u64 acc[4];
#pragma unroll
    for (int c = 0; c < 4; c++) acc[c] = pack2(0.f, 0.f);

    int am = t >> 3, ak = (t & 7) * 2;
    int bk = t >> 3, bn = (t & 7) * 8;
    unsigned sa = (unsigned)__cvta_generic_to_shared(As + ty * 2);

    for (int kt = k0; kt < k1; kt += BK) {
        {
            int gr = row0 + am;
            float2 av = make_float2(0.f, 0.f);
            if (gr < M) av = *(const float2*)(A + (size_t)gr * K + kt + ak);
            As[ak * BM + am] = av.x;
            As[(ak + 1) * BM + am] = av.y;
        }
        {
            const float4* bp = (const float4*)(B + (size_t)(kt + bk) * N + col0 + bn);
            *(float4*)(Bs + bk * BN + bn)     = bp[0];
            *(float4*)(Bs + bk * BN + bn + 4) = bp[1];
        }
        __syncthreads();
#pragma unroll
        for (int kk = 0; kk < BK; kk++) {
            u64 ap;
            asm("ld.shared.u64 %0,[%1];" : "=l"(ap) : "r"(sa + kk * (BM * 4)));
            float4 b4 = *(float4*)(Bs + kk * BN + tx * 4);
            ffma2(acc[0], ap, pack2(b4.x, b4.x));
            ffma2(acc[1], ap, pack2(b4.y, b4.y));
            ffma2(acc[2], ap, pack2(b4.z, b4.z));
            ffma2(acc[3], ap, pack2(b4.w, b4.w));
        }
        __syncthreads();
    }
    int gr0 = row0 + ty * 2, gr1 = gr0 + 1;
    float* op = out + (size_t)blockIdx.z * M * N;
#pragma unroll
    for (int c = 0; c < 4; c++) {
        float lo, hi; unpack2(acc[c], lo, hi);
        if (gr0 < M) op[gr0 * N + col0 + tx * 4 + c] = lo;
        if (gr1 < M) op[gr1 * N + col0 + tx * 4 + c] = hi;
    }
}

__global__ void reduce_bias_act_kernel(const float* __restrict__ part,
                                       const float* __restrict__ bias,
                                       float* __restrict__ out,
                                       int M, int N, int ns, int act) {
    int idx = blockIdx.x * blockDim.x + threadIdx.x;
    if (idx >= M * N) return;
    float s = 0.f;
    for (int z = 0; z < ns; z++) s += part[(size_t)z * M * N + idx];
    if (bias) s += bias[idx % N];
    if (act == 1) s = fmaxf(s, 0.f);
    out[idx] = s;
}

// ---------------- MEGA1: gemm1 partials | W3G | W3CH | prep ----------------
// grid: [0,1664) gemm1; [1664,1800) W3G; [1800,2057) W3CH; [2057,2257) prep
__global__ void __launch_bounds__(128)
mega1_kernel(const float* __restrict__ roi, const float* __restrict__ w1,
             const float* __restrict__ w3,  const float* __restrict__ b3,
             const float* __restrict__ wp2, const float* __restrict__ bp2,
             const float* __restrict__ wi,  const float* __restrict__ rootw,
             const float* __restrict__ bbox, const float* __restrict__ dirs,
             const float* __restrict__ we1, const float* __restrict__ be1,
             float* __restrict__ part, float* __restrict__ W3G,
             float* __restrict__ W3CH, float* __restrict__ Ag,
             float* __restrict__ Bg) {
    __shared__ __align__(16) float sh[1792];
    float* As = sh;          // [BK][BM]
    float* Bs = sh + 256;    // [BK][BN]
    int bx = blockIdx.x, t = threadIdx.x;

    if (bx < 1664) {
        // ---- gemm1 partial: roi[200,2048]@w1[2048,512], split16 ----
        int tx = t & 15, ty = t >> 4;
        int col0 = (bx & 7) * BN;
        int row0 = ((bx >> 3) % 13) * BM;
        int z = bx / 104;
        int k0 = z * 128, k1 = k0 + 128;
        u64 acc[4];
#pragma unroll
        for (int c = 0; c < 4; c++) acc[c] = pack2(0.f, 0.f);
        int am = t >> 3, ak = (t & 7) * 2;
        int bk = t >> 3, bn = (t & 7) * 8;
        unsigned sa = (unsigned)__cvta_generic_to_shared(As + ty * 2);
        for (int kt = k0; kt < k1; kt += BK) {
            int gr = row0 + am;
            float2 av = make_float2(0.f, 0.f);
            if (gr < N_NODES) av = *(const float2*)(roi + (size_t)gr * 2048 + kt + ak);
            As[ak * BM + am] = av.x;
            As[(ak + 1) * BM + am] = av.y;
            const float4* bp = (const float4*)(w1 + (size_t)(kt + bk) * 512 + col0 + bn);
            *(float4*)(Bs + bk * BN + bn)     = bp[0];
            *(float4*)(Bs + bk * BN + bn + 4) = bp[1];
            __syncthreads();
#pragma unroll
            for (int kk = 0; kk < BK; kk++) {
                u64 ap;
                asm("ld.shared.u64 %0,[%1];" : "=l"(ap) : "r"(sa + kk * (BM * 4)));
                float4 b4 = *(float4*)(Bs + kk * BN + tx * 4);
                ffma2(acc[0], ap, pack2(b4.x, b4.x));
                ffma2(acc[1], ap, pack2(b4.y, b4.y));
                ffma2(acc[2], ap, pack2(b4.z, b4.z));
                ffma2(acc[3], ap, pack2(b4.w, b4.w));
            }
            __syncthreads();
        }
        int gr0 = row0 + ty * 2, gr1 = gr0 + 1;
        float* op = part + (size_t)z * N_NODES * 512;
#pragma unroll
        for (int c = 0; c < 4; c++) {
            float lo, hi; unpack2(acc[c], lo, hi);
            if (gr0 < N_NODES) op[gr0 * 512 + col0 + tx * 4 + c] = lo;
            if (gr1 < N_NODES) op[gr1 * 512 + col0 + tx * 4 + c] = hi;
        }
    } else if (bx < 1800) {
        // ---- W3G[257,512] = [w3;b3] @ Wp2p   (Wp2p[i,r]=wp2[(r>>2)*4096+i*4+(r&3)]) ----
        int idx = bx - 1664;
        int tx = t & 15, ty = t >> 4;
        int col0 = (idx & 7) * BN;
        int row0 = (idx >> 3) * BM;          // 0..16 -> up to 271, guard 257
        u64 acc[4];
#pragma unroll
        for (int c = 0; c < 4; c++) acc[c] = pack2(0.f, 0.f);
        int am = t >> 3, ak = (t & 7) * 2;
        int bk = t >> 3, bn = (t & 7) * 8;
        unsigned sa = (unsigned)__cvta_generic_to_shared(As + ty * 2);
        for (int kt = 0; kt < 1024; kt += BK) {
            int gr = row0 + am;
            float2 av = make_float2(0.f, 0.f);
            if (gr < 256)       av = *(const float2*)(w3 + (size_t)gr * 1024 + kt + ak);
            else if (gr == 256) av = *(const float2*)(b3 + kt + ak);
            As[ak * BM + am] = av.x;
            As[(ak + 1) * BM + am] = av.y;
            {
                int i = kt + bk;
                int h0 = (col0 + bn) >> 2;
                float4 fa = *(const float4*)(wp2 + (size_t)h0 * 4096 + i * 4);
                float4 fb = *(const float4*)(wp2 + (size_t)(h0 + 1) * 4096 + i * 4);
                *(float4*)(Bs + bk * BN + bn)     = fa;
                *(float4*)(Bs + bk * BN + bn + 4) = fb;
            }
            __syncthreads();
#pragma unroll
            for (int kk = 0; kk < BK; kk++) {
                u64 ap;
                asm("ld.shared.u64 %0,[%1];" : "=l"(ap) : "r"(sa + kk * (BM * 4)));
                float4 b4 = *(float4*)(Bs + kk * BN + tx * 4);
                ffma2(acc[0], ap, pack2(b4.x, b4.x));
                ffma2(acc[1], ap, pack2(b4.y, b4.y));
                ffma2(acc[2], ap, pack2(b4.z, b4.z));
                ffma2(acc[3], ap, pack2(b4.w, b4.w));
            }
            __syncthreads();
        }
        int gr0 = row0 + ty * 2, gr1 = gr0 + 1;
#pragma unroll
        for (int c = 0; c < 4; c++) {
            float lo, hi; unpack2(acc[c], lo, hi);
            if (gr0 < 257) W3G[gr0 * 512 + col0 + tx * 4 + c] = lo;
            if (gr1 < 257) W3G[gr1 * 512 + col0 + tx * 4 + c] = hi;
        }
    } else if (bx < 2057) {
        // ---- W3CH[257,12] = [w3;b3] @ [bp2r | wi | rootw] ----
        int gr = bx - 1800;
        float acc[12];
#pragma unroll
        for (int c = 0; c < 12; c++) acc[c] = 0.f;
        for (int i = t; i < 1024; i += 128) {
            float a = (gr < 256) ? w3[(size_t)gr * 1024 + i] : b3[i];
            float4 p = *(const float4*)(bp2 + i * 4);
            float4 q = *(const float4*)(wi + i * 4);
            float4 r = *(const float4*)(rootw + i * 4);
            acc[0] += a * p.x; acc[1] += a * p.y; acc[2]  += a * p.z; acc[3]  += a * p.w;
            acc[4] += a * q.x; acc[5] += a * q.y; acc[6]  += a * q.z; acc[7]  += a * q.w;
            acc[8] += a * r.x; acc[9] += a * r.y; acc[10] += a * r.z; acc[11] += a * r.w;
        }
#pragma unroll
        for (int c = 0; c < 12; c++) sh[t * 12 + c] = acc[c];
        __syncthreads();
        for (int s = 64; s > 0; s >>= 1) {
            if (t < s)
#pragma unroll
                for (int c = 0; c < 12; c++) sh[t * 12 + c] += sh[(t + s) * 12 + c];
            __syncthreads();
        }
        if (t < 12) W3CH[gr * 12 + t] = sh[t];
    } else {
        // ---- prep: per-node separable edge-layer1 ----
        int n = bx - 2057;
        float attr[8];
#pragma unroll
        for (int k = 0; k < 4; k++) attr[k] = bbox[n * 4 + k] * (1.0f / 1024.0f);
#pragma unroll
        for (int k = 0; k < 4; k++) attr[4 + k] = dirs[n * 4 + k];
#pragma unroll
        for (int half = 0; half < 2; half++) {
            int u = t + half * 128;
            float a = be1[u], b = 0.f;
#pragma unroll
            for (int k = 0; k < 8; k++) {
                a += attr[k] * we1[k * 256 + u];
                b += attr[k] * we1[(8 + k) * 256 + u];
            }
            Ag[n * 256 + u] = a;
            Bg[n * 256 + u] = b;
        }
    }
}

// ---------------- MEGA2: G gemm | P heads ----------------
// grid: [0,104) G; [104,304) P
__global__ void __launch_bounds__(128)
mega2_kernel(const float* __restrict__ h2, const float* __restrict__ W3G,
             const float* __restrict__ W3CH, const float* __restrict__ bi,
             float* __restrict__ G, float* __restrict__ c,
             float* __restrict__ P, float* __restrict__ out2) {
    __shared__ __align__(16) float sh[1792];
    int bx = blockIdx.x, t = threadIdx.x;
    if (bx < 104) {
        float* As = sh;
        float* Bs = sh + 256;
        int tx = t & 15, ty = t >> 4;
        int col0 = (bx & 7) * BN;
        int row0 = (bx >> 3) * BM;
        u64 acc[4];
#pragma unroll
        for (int q = 0; q < 4; q++) acc[q] = pack2(0.f, 0.f);
        int am = t >> 3, ak = (t & 7) * 2;
        int bk = t >> 3, bn = (t & 7) * 8;
        unsigned sa = (unsigned)__cvta_generic_to_shared(As + ty * 2);
        for (int kt = 0; kt < 256; kt += BK) {
            int gr = row0 + am;
            float2 av = make_float2(0.f, 0.f);
            if (gr < N_NODES) av = *(const float2*)(h2 + (size_t)gr * 256 + kt + ak);
            As[ak * BM + am] = av.x;
            As[(ak + 1) * BM + am] = av.y;
            const float4* bp = (const float4*)(W3G + (size_t)(kt + bk) * 512 + col0 + bn);
            *(float4*)(Bs + bk * BN + bn)     = bp[0];
            *(float4*)(Bs + bk * BN + bn + 4) = bp[1];
            __syncthreads();
#pragma unroll
            for (int kk = 0; kk < BK; kk++) {
                u64 ap;
                asm("ld.shared.u64 %0,[%1];" : "=l"(ap) : "r"(sa + kk * (BM * 4)));
                float4 b4 = *(float4*)(Bs + kk * BN + tx * 4);
                ffma2(acc[0], ap, pack2(b4.x, b4.x));
                ffma2(acc[1], ap, pack2(b4.y, b4.y));
                ffma2(acc[2], ap, pack2(b4.z, b4.z));
                ffma2(acc[3], ap, pack2(b4.w, b4.w));
            }
            __syncthreads();
        }
        int gr0 = row0 + ty * 2, gr1 = gr0 + 1;
#pragma unroll
        for (int q = 0; q < 4; q++) {
            float lo, hi; unpack2(acc[q], lo, hi);
            float bv = W3G[256 * 512 + col0 + tx * 4 + q];
            if (gr0 < N_NODES) G[gr0 * 512 + col0 + tx * 4 + q] = lo + bv;
            if (gr1 < N_NODES) G[gr1 * 512 + col0 + tx * 4 + q] = hi + bv;
        }
    } else {
        int n = bx - 104;
        float acc[12];
#pragma unroll
        for (int q = 0; q < 12; q++) acc[q] = 0.f;
        for (int i = t; i < 256; i += 128) {
            float a = h2[n * 256 + i];
            float4 w0 = *(const float4*)(W3CH + i * 12);
            float4 w1v = *(const float4*)(W3CH + i * 12 + 4);
            float4 w2v = *(const float4*)(W3CH + i * 12 + 8);
            acc[0] += a * w0.x;  acc[1] += a * w0.y;  acc[2]  += a * w0.z;  acc[3]  += a * w0.w;
            acc[4] += a * w1v.x; acc[5] += a * w1v.y; acc[6]  += a * w1v.z; acc[7]  += a * w1v.w;
            acc[8] += a * w2v.x; acc[9] += a * w2v.y; acc[10] += a * w2v.z; acc[11] += a * w2v.w;
        }
#pragma unroll
        for (int q = 0; q < 12; q++) sh[t * 12 + q] = acc[q];
        __syncthreads();
        for (int s = 64; s > 0; s >>= 1) {
            if (t < s)
#pragma unroll
                for (int q = 0; q < 12; q++) sh[t * 12 + q] += sh[(t + s) * 12 + q];
            __syncthreads();
        }
        if (t == 0) {
#pragma unroll
            for (int o = 0; o < 4; o++) {
                c[n * 4 + o] = sh[o] + W3CH[256 * 12 + o];
                float cv = sh[4 + o] + W3CH[256 * 12 + 4 + o] + bi[o];
                out2[n * 4 + o] = 1.f / (1.f + expf(-cv));
                P[n * 4 + o] = sh[8 + o] + W3CH[256 * 12 + 8 + o];
            }
        }
    }
}

// ---------------- fused edge kernel (64 edges / block) ----------------
__global__ void __launch_bounds__(256)
edge_kernel(const float* __restrict__ Ag, const float* __restrict__ Bg,
            const float* __restrict__ pri,
            const float* __restrict__ we2, const float* __restrict__ be2,
            const float* __restrict__ we3, const float* __restrict__ be3,
            const float* __restrict__ wp1, const float* __restrict__ bp1,
            const float* __restrict__ G,  const float* __restrict__ c,
            float* __restrict__ edge_out, float* __restrict__ msg) {
    __shared__ __align__(16) float sbuf[8448];
    __shared__ float s_G[1024];
    __shared__ float s_e4[256];
    __shared__ float s_A[512];
    __shared__ int s_src[64], s_dst[64];

    int t = threadIdx.x;
    int base = blockIdx.x * 64;
    int src0 = base / NM1;
    int last = min(base + 63, E_TOT - 1);
    int src1 = last / NM1;

    if (t < 64) {
        int ge = base + t;
        int i = src0, j = 0;
        if (ge < E_TOT) {
            i = ge / NM1;
            int r = ge - i * NM1;
            j = (r < i) ? r : r + 1;
        }
        s_src[t] = i; s_dst[t] = j;
    }
    for (int idx = t; idx < 512; idx += 256) {
        int row = idx >> 8, k = idx & 255;
        s_A[idx] = Ag[(row ? src1 : src0) * 256 + k];
    }
    __syncthreads();

    int e0 = (t >> 4) * 4;
    int v0 = (t & 15) * 4;
    u64 acc01[4], acc23[4];
#pragma unroll
    for (int cq = 0; cq < 4; cq++) {
        float b = be2[v0 + cq];
        acc01[cq] = pack2(b, b);
        acc23[cq] = pack2(b, b);
    }
    unsigned h1base = (unsigned)__cvta_generic_to_shared(sbuf + e0);

    for (int uc = 0; uc < 4; uc++) {
        for (int idx = t; idx < 4096; idx += 256) {
            int e = idx >> 6, jj = idx & 63;
            int u = uc * 64 + jj;
            float val = 0.f;
            int ge = base + e;
            if (ge < E_TOT) {
                int aoff = (s_src[e] == src0) ? 0 : 256;
                val = fmaxf(s_A[aoff + u] + Bg[s_dst[e] * 256 + u], 0.f);
            }
            sbuf[jj * 68 + e] = val;
        }
        for (int idx = t; idx < 4096; idx += 256) {
            int jj = idx >> 6, v = idx & 63;
            sbuf[4352 + jj * 64 + v] = we2[(uc * 64 + jj) * 64 + v];
        }
        __syncthreads();
#pragma unroll 8
        for (int jj = 0; jj < 64; jj++) {
            u64 h01, h23;
            asm("ld.shared.v2.u64 {%0,%1},[%2];"
                : "=l"(h01), "=l"(h23) : "r"(h1base + jj * 272));
            float4 w4 = *(float4*)(sbuf + 4352 + jj * 64 + v0);
            u64 wx = pack2(w4.x, w4.x), wy = pack2(w4.y, w4.y);
            u64 wz = pack2(w4.z, w4.z), ww = pack2(w4.w, w4.w);
            ffma2(acc01[0], h01, wx); ffma2(acc23[0], h23, wx);
            ffma2(acc01[1], h01, wy); ffma2(acc23[1], h23, wy);
            ffma2(acc01[2], h01, wz); ffma2(acc23[2], h23, wz);
            ffma2(acc01[3], h01, ww); ffma2(acc23[3], h23, ww);
        }
        __syncthreads();
    }

#pragma unroll
    for (int cq = 0; cq < 4; cq++) {
        float lo, hi;
        unpack2(acc01[cq], lo, hi);
        sbuf[(e0 + 0) * 64 + v0 + cq] = fmaxf(lo, 0.f);
        sbuf[(e0 + 1) * 64 + v0 + cq] = fmaxf(hi, 0.f);
        unpack2(acc23[cq], lo, hi);
        sbuf[(e0 + 2) * 64 + v0 + cq] = fmaxf(lo, 0.f);
        sbuf[(e0 + 3) * 64 + v0 + cq] = fmaxf(hi, 0.f);
    }
    __syncthreads();

    if (t < 192) {
        int e = t / 3, w = t - e * 3;
        float a = be3[w];
        for (int v = 0; v < 64; v++) a += sbuf[e * 64 + v] * we3[v * 3 + w];
        float sg = 1.f / (1.f + expf(-a));
        s_e4[e * 4 + w] = sg;
        int ge = base + e;
        if (ge < E_TOT) edge_out[ge * 4 + w] = sg;
    } else {
        int e = t - 192;
        int ge = base + e;
        float hp = 0.f;
        if (ge < E_TOT) hp = (pri[s_src[e]] > pri[s_dst[e]]) ? 1.f : 0.f;
        s_e4[e * 4 + 3] = hp;
        if (ge < E_TOT) edge_out[ge * 4 + 3] = hp;
    }
    __syncthreads();

    {
        int h = t & 127, eg = t >> 7;
        float w0 = wp1[h], w1v = wp1[128 + h], w2v = wp1[256 + h], w3v = wp1[384 + h];
        float b = bp1[h];
#pragma unroll 4
        for (int s = 0; s < 32; s++) {
            int e = eg * 32 + s;
            float a = b + s_e4[e * 4 + 0] * w0 + s_e4[e * 4 + 1] * w1v
                        + s_e4[e * 4 + 2] * w2v + s_e4[e * 4 + 3] * w3v;
            sbuf[e * 129 + h] = fmaxf(a, 0.f);
        }
    }
    for (int idx = t; idx < 1024; idx += 256)
        s_G[idx] = G[((idx < 512) ? src0 : src1) * 512 + (idx & 511)];
    __syncthreads();

    {
        int e = t >> 2, o = t & 3;
        int ge = base + e;
        if (ge < E_TOT) {
            int src = s_src[e];
            int roff = (src == src0) ? 0 : 512;
            float a = c[src * 4 + o];
            const float* hp = sbuf + e * 129;
            const float* gp = s_G + roff + o;
#pragma unroll 8
            for (int h = 0; h < 128; h++) a += hp[h] * gp[h * 4];
            msg[ge * 4 + o] = a;
        }
    }
}

// ---------------- final: agg over dst + root head ----------------
__global__ void final_kernel(const float* __restrict__ msg,
                             const float* __restrict__ P,
                             const float* __restrict__ rootb,
                             float* __restrict__ out) {
    int j = blockIdx.x, t = threadIdx.x;
    float a[4] = {0.f, 0.f, 0.f, 0.f};
    if (t < N_NODES && t != j) {
        int i = t;
        int pos = (j < i) ? j : j - 1;
        int e = i * NM1 + pos;
        float4 m = *(const float4*)(msg + e * 4);
        a[0] = m.x; a[1] = m.y; a[2] = m.z; a[3] = m.w;
    }
    __shared__ float red[256 * 4];
#pragma unroll
    for (int q = 0; q < 4; q++) red[t * 4 + q] = a[q];
    __syncthreads();
    for (int s = 128; s > 0; s >>= 1) {
        if (t < s)
#pragma unroll
            for (int q = 0; q < 4; q++) red[t * 4 + q] += red[(t + s) * 4 + q];
        __syncthreads();
    }
    if (t < 4) out[j * 4 + t] = red[t] + P[j * 4 + t] + rootb[t];
}

// ---------------- launcher ----------------
extern "C" void kernel_launch(void* const* d_in, const int* in_sizes, int n_in,
                              void* d_out, int out_size) {
    const float* roi   = (const float*)d_in[0];
    const float* bbox  = (const float*)d_in[1];
    const float* dirs  = (const float*)d_in[2];
    const float* pri   = (const float*)d_in[3];
    const float* w1    = (const float*)d_in[4];
    const float* b1    = (const float*)d_in[5];
    const float* w2    = (const float*)d_in[6];
    const float* b2    = (const float*)d_in[7];
    const float* w3    = (const float*)d_in[8];
    const float* b3    = (const float*)d_in[9];
    const float* wi    = (const float*)d_in[10];
    const float* bi    = (const float*)d_in[11];
    const float* we1   = (const float*)d_in[12];
    const float* be1   = (const float*)d_in[13];
    const float* we2   = (const float*)d_in[14];
    const float* be2   = (const float*)d_in[15];
    const float* we3   = (const float*)d_in[16];
    const float* be3   = (const float*)d_in[17];
    const float* wp1   = (const float*)d_in[18];
    const float* bp1   = (const float*)d_in[19];
    const float* wp2   = (const float*)d_in[20];
    const float* bp2   = (const float*)d_in[21];
    const float* rootw = (const float*)d_in[22];
    const float* rootb = (const float*)d_in[23];
    float* out = (float*)d_out;

    float *pPart, *pH1, *pH2, *pG, *pC, *pP, *pMsg, *pW3G, *pW3CH, *pA, *pB;
    cudaGetSymbolAddress((void**)&pPart,  g_part);
    cudaGetSymbolAddress((void**)&pH1,    g_h1);
    cudaGetSymbolAddress((void**)&pH2,    g_h2);
    cudaGetSymbolAddress((void**)&pG,     g_G);
    cudaGetSymbolAddress((void**)&pC,     g_c);
    cudaGetSymbolAddress((void**)&pP,     g_P);
    cudaGetSymbolAddress((void**)&pMsg,   g_msg);
    cudaGetSymbolAddress((void**)&pW3G,   g_W3G);
    cudaGetSymbolAddress((void**)&pW3CH,  g_W3CH);
    cudaGetSymbolAddress((void**)&pA,     g_A);
    cudaGetSymbolAddress((void**)&pB,     g_B);

    // 1: prep + W3G + W3CH + gemm1 partials
    mega1_kernel<<<2257, 128>>>(roi, w1, w3, b3, wp2, bp2, wi, rootw,
                                bbox, dirs, we1, be1,
                                pPart, pW3G, pW3CH, pA, pB);
    // 2: h1 = relu(sum + b1)
    reduce_bias_act_kernel<<<(N_NODES * 512 + 255) / 256, 256>>>(pPart, b1, pH1, N_NODES, 512, 16, 1);
    // 3: gemm2 partials: h1@w2, split8
    {
        dim3 g(256 / BN, 13, 8);
        gemm_kernel<<<g, 128>>>(pH1, w2, pPart, N_NODES, 256, 512, 8);
    }
    // 4: h2 = relu(sum + b2)
    reduce_bias_act_kernel<<<(N_NODES * 256 + 255) / 256, 256>>>(pPart, b2, pH2, N_NODES, 256, 8, 1);
    // 5: G + heads (c, concepts-out, P)
    mega2_kernel<<<304, 128>>>(pH2, pW3G, pW3CH, bi, pG, pC, pP, out + 800);
    // 6: edges
    edge_kernel<<<(E_TOT + 63) / 64, 256>>>(pA, pB, pri, we2, be2, we3, be3,
                                            wp1, bp1, pG, pC, out + 1600, pMsg);
    // 7: aggregate + root
    final_kernel<<<N_NODES, 256>>>(pMsg, pP, rootb, out);
}

// round 5
// speedup vs baseline: 1.1314x; 1.1314x over previous
#include <cuda_runtime.h>
#include <math.h>

#define N_NODES 200
#define NM1     199
#define E_TOT   39800

typedef unsigned long long u64;

__device__ __forceinline__ u64 pack2(float lo, float hi) {
    u64 r; asm("mov.b64 %0,{%1,%2};" : "=l"(r) : "f"(lo), "f"(hi)); return r;
}
__device__ __forceinline__ void unpack2(u64 v, float& lo, float& hi) {
    asm("mov.b64 {%0,%1},%2;" : "=f"(lo), "=f"(hi) : "l"(v));
}
__device__ __forceinline__ void ffma2(u64& d, u64 a, u64 b) {
    asm("fma.rn.f32x2 %0,%1,%2,%0;" : "+l"(d) : "l"(a), "l"(b));
}

// ---------------- scratch (device globals; no allocation) ----------------
__device__ __align__(16) float g_part[16 * 200 * 512];
__device__ __align__(16) float g_wgp [4 * 257 * 512];
__device__ __align__(16) float g_h1[200 * 512];
__device__ __align__(16) float g_h2[200 * 256];
__device__ __align__(16) float g_G [200 * 512];
__device__ __align__(16) float g_c [200 * 4];
__device__ __align__(16) float g_P [200 * 4];
__device__ __align__(16) float g_msg[E_TOT * 4];
__device__ __align__(16) float g_W3G [257 * 512];
__device__ __align__(16) float g_W3CH[257 * 12];
__device__ __align__(16) float g_Ae[200 * 256];
__device__ __align__(16) float g_Be[200 * 256];
__device__ __align__(16) float g_w3b3[257 * 1024];
__device__ __align__(16) float g_wp2p[1024 * 512];

__device__ volatile unsigned g_bar_gen = 0;
__device__ unsigned g_bar_cnt = 0;

__device__ __forceinline__ void grid_barrier() {
    __threadfence();
    __syncthreads();
    if (threadIdx.x == 0) {
        unsigned gen = g_bar_gen;
        unsigned a = atomicAdd(&g_bar_cnt, 1u);
        if (a == gridDim.x - 1) {
            g_bar_cnt = 0u;
            __threadfence();
            g_bar_gen = gen + 1u;
        } else {
            while (g_bar_gen == gen) { __nanosleep(64); }
        }
    }
    __syncthreads();
}

// ---------------- 256-thread GEMM tile: 16 rows x 128 cols ----------------
// writes out[row*ldo+col] (+bias if non-null). K range [k0,k1), step 16.
__device__ void gemm_tile(const float* __restrict__ A, int lda,
                          const float* __restrict__ B, int ldb,
                          float* __restrict__ outp, int ldo, int M,
                          int col0, int row0, int k0, int k1,
                          const float* __restrict__ bias, float* sh) {
    float* As = sh;          // [16k][16m]
    float* Bs = sh + 256;    // [16k][128n]
    int t = threadIdx.x;
    int tx = t & 31, ty = t >> 5;
    u64 acc[4];
#pragma unroll
    for (int c = 0; c < 4; c++) acc[c] = pack2(0.f, 0.f);
    int am = t >> 4, ak = t & 15;
    int bk = t >> 4, bn = (t & 15) * 8;
    unsigned sa = (unsigned)__cvta_generic_to_shared(As + ty * 2);

    for (int kt = k0; kt < k1; kt += 16) {
        {
            int gr = row0 + am;
            float av = (gr < M) ? A[(size_t)gr * lda + kt + ak] : 0.f;
            As[ak * 16 + am] = av;
        }
        {
            const float4* bp = (const float4*)(B + (size_t)(kt + bk) * ldb + col0 + bn);
            *(float4*)(Bs + bk * 128 + bn)     = bp[0];
            *(float4*)(Bs + bk * 128 + bn + 4) = bp[1];
        }
        __syncthreads();
#pragma unroll
        for (int kk = 0; kk < 16; kk++) {
            u64 ap;
            asm("ld.shared.u64 %0,[%1];" : "=l"(ap) : "r"(sa + kk * 64));
            float4 b4 = *(float4*)(Bs + kk * 128 + tx * 4);
            ffma2(acc[0], ap, pack2(b4.x, b4.x));
            ffma2(acc[1], ap, pack2(b4.y, b4.y));
            ffma2(acc[2], ap, pack2(b4.z, b4.z));
            ffma2(acc[3], ap, pack2(b4.w, b4.w));
        }
        __syncthreads();
    }
    int gr0 = row0 + ty * 2, gr1 = gr0 + 1;
#pragma unroll
    for (int c = 0; c < 4; c++) {
        float lo, hi; unpack2(acc[c], lo, hi);
        float bv = bias ? bias[col0 + tx * 4 + c] : 0.f;
        lo += bv; hi += bv;
        if (gr0 < M) outp[(size_t)gr0 * ldo + col0 + tx * 4 + c] = lo;
        if (gr1 < M) outp[(size_t)gr1 * ldo + col0 + tx * 4 + c] = hi;
    }
}

// ---------------- the mega kernel ----------------
__global__ void __launch_bounds__(256, 4)
mega_kernel(const float* __restrict__ roi,  const float* __restrict__ bbox,
            const float* __restrict__ dirs, const float* __restrict__ pri,
            const float* __restrict__ w1,   const float* __restrict__ b1,
            const float* __restrict__ w2,   const float* __restrict__ b2,
            const float* __restrict__ w3,   const float* __restrict__ b3,
            const float* __restrict__ wi,   const float* __restrict__ bi,
            const float* __restrict__ we1,  const float* __restrict__ be1,
            const float* __restrict__ we2,  const float* __restrict__ be2,
            const float* __restrict__ we3,  const float* __restrict__ be3,
            const float* __restrict__ wp1,  const float* __restrict__ bp1,
            const float* __restrict__ wp2,  const float* __restrict__ bp2,
            const float* __restrict__ rootw, const float* __restrict__ rootb,
            float* __restrict__ out) {
    __shared__ __align__(16) float sh[10624];
    int t = threadIdx.x;
    int gstride = gridDim.x;

    // ================= P0: gemm1 partials | permute wp2 | prep | W3CH | w3b3 =====
    for (int task = blockIdx.x; task < 3341; task += gstride) {
        if (task < 832) {
            int col0 = (task & 3) * 128;
            int row0 = ((task >> 2) % 13) * 16;
            int z = task / 52;
            gemm_tile(roi, 2048, w1, 512, g_part + (size_t)z * 102400, 512,
                      N_NODES, col0, row0, z * 128, z * 128 + 128, nullptr, sh);
        } else if (task < 1856) {
            int base = (task - 832) * 512;
#pragma unroll
            for (int q = 0; q < 2; q++) {
                int idx = base + t + q * 256;
                int i = idx >> 9, r = idx & 511;
                g_wp2p[idx] = wp2[(size_t)(r >> 2) * 4096 + i * 4 + (r & 3)];
            }
        } else if (task < 2056) {
            int n = task - 1856;
            float attr[8];
#pragma unroll
            for (int k = 0; k < 4; k++) attr[k] = bbox[n * 4 + k] * (1.0f / 1024.0f);
#pragma unroll
            for (int k = 0; k < 4; k++) attr[4 + k] = dirs[n * 4 + k];
            int u = t;
            float a = be1[u], b = 0.f;
#pragma unroll
            for (int k = 0; k < 8; k++) {
                a += attr[k] * we1[k * 256 + u];
                b += attr[k] * we1[(8 + k) * 256 + u];
            }
            g_Ae[n * 256 + u] = a;
            g_Be[n * 256 + u] = b;
        } else if (task < 2313) {
            int gr = task - 2056;
            float acc[12];
#pragma unroll
            for (int c = 0; c < 12; c++) acc[c] = 0.f;
            for (int i = t; i < 1024; i += 256) {
                float a = (gr < 256) ? w3[(size_t)gr * 1024 + i] : b3[i];
                float4 p = *(const float4*)(bp2 + i * 4);
                float4 q = *(const float4*)(wi + i * 4);
                float4 r = *(const float4*)(rootw + i * 4);
                acc[0] += a * p.x; acc[1] += a * p.y; acc[2]  += a * p.z; acc[3]  += a * p.w;
                acc[4] += a * q.x; acc[5] += a * q.y; acc[6]  += a * q.z; acc[7]  += a * q.w;
                acc[8] += a * r.x; acc[9] += a * r.y; acc[10] += a * r.z; acc[11] += a * r.w;
            }
#pragma unroll
            for (int c = 0; c < 12; c++) sh[t * 12 + c] = acc[c];
            __syncthreads();
            for (int s = 128; s > 0; s >>= 1) {
                if (t < s)
#pragma unroll
                    for (int c = 0; c < 12; c++) sh[t * 12 + c] += sh[(t + s) * 12 + c];
                __syncthreads();
            }
            if (t < 12) g_W3CH[gr * 12 + t] = sh[t];
            __syncthreads();
        } else {
            int idx = (task - 2313) * 256 + t;
            if (idx < 257 * 1024) {
                int row = idx >> 10, col = idx & 1023;
                g_w3b3[idx] = (row < 256) ? w3[(size_t)row * 1024 + col] : b3[col];
            }
        }
    }
    grid_barrier();

    // ================= P1: reduce1 -> h1 | W3G partials =================
    for (int task = blockIdx.x; task < 672; task += gstride) {
        if (task < 400) {
            int idx = task * 256 + t;
            float s = 0.f;
#pragma unroll
            for (int z = 0; z < 16; z++) s += g_part[(size_t)z * 102400 + idx];
            g_h1[idx] = fmaxf(s + b1[idx & 511], 0.f);
        } else {
            int w = task - 400;
            int col0 = (w & 3) * 128;
            int row0 = ((w >> 2) % 17) * 16;
            int z = w / 68;
            gemm_tile(g_w3b3, 1024, g_wp2p, 512, g_wgp + (size_t)z * 131584, 512,
                      257, col0, row0, z * 256, z * 256 + 256, nullptr, sh);
        }
    }
    grid_barrier();

    // ================= P2: gemm2 partials | W3G reduce =================
    for (int task = blockIdx.x; task < 722; task += gstride) {
        if (task < 208) {
            int col0 = (task & 1) * 128;
            int row0 = ((task >> 1) % 13) * 16;
            int z = task / 26;
            gemm_tile(g_h1, 512, w2, 256, g_part + (size_t)z * 51200, 256,
                      N_NODES, col0, row0, z * 64, z * 64 + 64, nullptr, sh);
        } else {
            int idx = (task - 208) * 256 + t;
            if (idx < 257 * 512) {
                float s = 0.f;
#pragma unroll
                for (int z = 0; z < 4; z++) s += g_wgp[(size_t)z * 131584 + idx];
                g_W3G[idx] = s;
            }
        }
    }
    grid_barrier();

    // ================= P3: reduce2 -> h2 =================
    for (int task = blockIdx.x; task < 200; task += gstride) {
        int idx = task * 256 + t;
        float s = 0.f;
#pragma unroll
        for (int z = 0; z < 8; z++) s += g_part[(size_t)z * 51200 + idx];
        g_h2[idx] = fmaxf(s + b2[idx & 255], 0.f);
    }
    grid_barrier();

    // ================= P4: G = h2 @ W3G (+bias row) | heads =================
    for (int task = blockIdx.x; task < 252; task += gstride) {
        if (task < 52) {
            int col0 = (task & 3) * 128;
            int row0 = (task >> 2) * 16;
            gemm_tile(g_h2, 256, g_W3G, 512, g_G, 512, N_NODES,
                      col0, row0, 0, 256, g_W3G + 256 * 512, sh);
        } else {
            int n = task - 52;
            float a = g_h2[n * 256 + t];
            float4 w0  = *(const float4*)(g_W3CH + t * 12);
            float4 w1v = *(const float4*)(g_W3CH + t * 12 + 4);
            float4 w2v = *(const float4*)(g_W3CH + t * 12 + 8);
            float acc[12] = {a*w0.x, a*w0.y, a*w0.z, a*w0.w,
                             a*w1v.x, a*w1v.y, a*w1v.z, a*w1v.w,
                             a*w2v.x, a*w2v.y, a*w2v.z, a*w2v.w};
#pragma unroll
            for (int q = 0; q < 12; q++) sh[t * 12 + q] = acc[q];
            __syncthreads();
            for (int s = 128; s > 0; s >>= 1) {
                if (t < s)
#pragma unroll
                    for (int q = 0; q < 12; q++) sh[t * 12 + q] += sh[(t + s) * 12 + q];
                __syncthreads();
            }
            if (t == 0) {
#pragma unroll
                for (int o = 0; o < 4; o++) {
                    g_c[n * 4 + o] = sh[o] + g_W3CH[256 * 12 + o];
                    float cv = sh[4 + o] + g_W3CH[256 * 12 + 4 + o] + bi[o];
                    out[800 + n * 4 + o] = 1.f / (1.f + expf(-cv));
                    g_P[n * 4 + o] = sh[8 + o] + g_W3CH[256 * 12 + 8 + o];
                }
            }
            __syncthreads();
        }
    }
    grid_barrier();

    // ================= P5: edges (64 per task) =================
    {
        float* sbuf = sh;              // 8448
        float* s_G  = sh + 8448;       // 1024
        float* s_e4 = sh + 9472;       // 256
        float* s_A  = sh + 9728;       // 512
        int* s_src  = (int*)(sh + 10240);
        int* s_dst  = (int*)(sh + 10304);

        for (int et = blockIdx.x; et < 622; et += gstride) {
            int base = et * 64;
            int src0 = base / NM1;
            int last = min(base + 63, E_TOT - 1);
            int src1 = last / NM1;

            if (t < 64) {
                int ge = base + t;
                int i = src0, j = 0;
                if (ge < E_TOT) {
                    i = ge / NM1;
                    int r = ge - i * NM1;
                    j = (r < i) ? r : r + 1;
                }
                s_src[t] = i; s_dst[t] = j;
            }
            for (int idx = t; idx < 512; idx += 256) {
                int row = idx >> 8, k = idx & 255;
                s_A[idx] = g_Ae[(row ? src1 : src0) * 256 + k];
            }
            __syncthreads();

            int e0 = (t >> 4) * 4;
            int v0 = (t & 15) * 4;
            u64 acc01[4], acc23[4];
#pragma unroll
            for (int cq = 0; cq < 4; cq++) {
                float b = be2[v0 + cq];
                acc01[cq] = pack2(b, b);
                acc23[cq] = pack2(b, b);
            }
            unsigned h1base = (unsigned)__cvta_generic_to_shared(sbuf + e0);

            for (int uc = 0; uc < 4; uc++) {
                for (int idx = t; idx < 4096; idx += 256) {
                    int e = idx >> 6, jj = idx & 63;
                    int u = uc * 64 + jj;
                    float val = 0.f;
                    int ge = base + e;
                    if (ge < E_TOT) {
                        int aoff = (s_src[e] == src0) ? 0 : 256;
                        val = fmaxf(s_A[aoff + u] + g_Be[s_dst[e] * 256 + u], 0.f);
                    }
                    sbuf[jj * 68 + e] = val;
                }
                for (int idx = t; idx < 4096; idx += 256) {
                    int jj = idx >> 6, v = idx & 63;
                    sbuf[4352 + jj * 64 + v] = we2[(uc * 64 + jj) * 64 + v];
                }
                __syncthreads();
#pragma unroll 8
                for (int jj = 0; jj < 64; jj++) {
                    u64 h01, h23;
                    asm("ld.shared.v2.u64 {%0,%1},[%2];"
                        : "=l"(h01), "=l"(h23) : "r"(h1base + jj * 272));
                    float4 w4 = *(float4*)(sbuf + 4352 + jj * 64 + v0);
                    u64 wx = pack2(w4.x, w4.x), wy = pack2(w4.y, w4.y);
                    u64 wz = pack2(w4.z, w4.z), ww = pack2(w4.w, w4.w);
                    ffma2(acc01[0], h01, wx); ffma2(acc23[0], h23, wx);
                    ffma2(acc01[1], h01, wy); ffma2(acc23[1], h23, wy);
                    ffma2(acc01[2], h01, wz); ffma2(acc23[2], h23, wz);
                    ffma2(acc01[3], h01, ww); ffma2(acc23[3], h23, ww);
                }
                __syncthreads();
            }

#pragma unroll
            for (int cq = 0; cq < 4; cq++) {
                float lo, hi;
                unpack2(acc01[cq], lo, hi);
                sbuf[(e0 + 0) * 64 + v0 + cq] = fmaxf(lo, 0.f);
                sbuf[(e0 + 1) * 64 + v0 + cq] = fmaxf(hi, 0.f);
                unpack2(acc23[cq], lo, hi);
                sbuf[(e0 + 2) * 64 + v0 + cq] = fmaxf(lo, 0.f);
                sbuf[(e0 + 3) * 64 + v0 + cq] = fmaxf(hi, 0.f);
            }
            __syncthreads();

            if (t < 192) {
                int e = t / 3, w = t - e * 3;
                float a = be3[w];
                for (int v = 0; v < 64; v++) a += sbuf[e * 64 + v] * we3[v * 3 + w];
                float sg = 1.f / (1.f + expf(-a));
                s_e4[e * 4 + w] = sg;
                int ge = base + e;
                if (ge < E_TOT) out[1600 + ge * 4 + w] = sg;
            } else {
                int e = t - 192;
                int ge = base + e;
                float hp = 0.f;
                if (ge < E_TOT) hp = (pri[s_src[e]] > pri[s_dst[e]]) ? 1.f : 0.f;
                s_e4[e * 4 + 3] = hp;
                if (ge < E_TOT) out[1600 + ge * 4 + 3] = hp;
            }
            __syncthreads();

            {
                int h = t & 127, eg = t >> 7;
                float w0 = wp1[h], w1v = wp1[128 + h], w2v = wp1[256 + h], w3v = wp1[384 + h];
                float b = bp1[h];
#pragma unroll 4
                for (int s = 0; s < 32; s++) {
                    int e = eg * 32 + s;
                    float a = b + s_e4[e * 4 + 0] * w0 + s_e4[e * 4 + 1] * w1v
                                + s_e4[e * 4 + 2] * w2v + s_e4[e * 4 + 3] * w3v;
                    sbuf[e * 129 + h] = fmaxf(a, 0.f);
                }
            }
            for (int idx = t; idx < 1024; idx += 256)
                s_G[idx] = g_G[((idx < 512) ? src0 : src1) * 512 + (idx & 511)];
            __syncthreads();

            {
                int e = t >> 2, o = t & 3;
                int ge = base + e;
                if (ge < E_TOT) {
                    int src = s_src[e];
                    int roff = (src == src0) ? 0 : 512;
                    float a = g_c[src * 4 + o];
                    const float* hp = sbuf + e * 129;
                    const float* gp = s_G + roff + o;
#pragma unroll 8
                    for (int h = 0; h < 128; h++) a += hp[h] * gp[h * 4];
                    g_msg[ge * 4 + o] = a;
                }
            }
            __syncthreads();
        }
    }
    grid_barrier();

    // ================= P6: final aggregate + root head =================
    for (int task = blockIdx.x; task < 200; task += gstride) {
        int j = task;
        float a[4] = {0.f, 0.f, 0.f, 0.f};
        if (t < N_NODES && t != j) {
            int i = t;
            int pos = (j < i) ? j : j - 1;
            int e = i * NM1 + pos;
            float4 m = *(const float4*)(g_msg + e * 4);
            a[0] = m.x; a[1] = m.y; a[2] = m.z; a[3] = m.w;
        }
#pragma unroll
        for (int q = 0; q < 4; q++) sh[t * 4 + q] = a[q];
        __syncthreads();
        for (int s = 128; s > 0; s >>= 1) {
            if (t < s)
#pragma unroll
                for (int q = 0; q < 4; q++) sh[t * 4 + q] += sh[(t + s) * 4 + q];
            __syncthreads();
        }
        if (t < 4) out[j * 4 + t] = sh[t] + g_P[j * 4 + t] + rootb[t];
        __syncthreads();
    }
}

// ---------------- launcher ----------------
extern "C" void kernel_launch(void* const* d_in, const int* in_sizes, int n_in,
                              void* d_out, int out_size) {
    const float* roi   = (const float*)d_in[0];
    const float* bbox  = (const float*)d_in[1];
    const float* dirs  = (const float*)d_in[2];
    const float* pri   = (const float*)d_in[3];
    const float* w1    = (const float*)d_in[4];
    const float* b1    = (const float*)d_in[5];
    const float* w2    = (const float*)d_in[6];
    const float* b2    = (const float*)d_in[7];
    const float* w3    = (const float*)d_in[8];
    const float* b3    = (const float*)d_in[9];
    const float* wi    = (const float*)d_in[10];
    const float* bi    = (const float*)d_in[11];
    const float* we1   = (const float*)d_in[12];
    const float* be1   = (const float*)d_in[13];
    const float* we2   = (const float*)d_in[14];
    const float* be2   = (const float*)d_in[15];
    const float* we3   = (const float*)d_in[16];
    const float* be3   = (const float*)d_in[17];
    const float* wp1   = (const float*)d_in[18];
    const float* bp1   = (const float*)d_in[19];
    const float* wp2   = (const float*)d_in[20];
    const float* bp2   = (const float*)d_in[21];
    const float* rootw = (const float*)d_in[22];
    const float* rootb = (const float*)d_in[23];
    float* out = (float*)d_out;

    // co-residency-safe grid size (host-side queries; capture-safe, deterministic)
    int dev = 0;
    cudaGetDevice(&dev);
    int nsm = 148;
    cudaDeviceGetAttribute(&nsm, cudaDevAttrMultiProcessorCount, dev);
    int occ = 1;
    cudaOccupancyMaxActiveBlocksPerMultiprocessor(&occ, mega_kernel, 256, 0);
    if (occ < 1) occ = 1;
    long long grid = (long long)occ * nsm;
    if (grid > 1184) grid = 1184;   // no benefit beyond ~2x task counts

    mega_kernel<<<(int)grid, 256>>>(roi, bbox, dirs, pri,
                                    w1, b1, w2, b2, w3, b3, wi, bi,
                                    we1, be1, we2, be2, we3, be3,
                                    wp1, bp1, wp2, bp2, rootw, rootb, out);
}